// round 1
// baseline (speedup 1.0000x reference)
#include <cuda_runtime.h>
#include <cuda_bf16.h>
#include <math.h>
#include <float.h>

// ---------------------------------------------------------------------------
// MultiLabelGCN on GB300.
// Pipeline (per layer): T = A_hat * H   (A_hat baked, per-graph 33x33)
//                       Z = T @ W + b   (dense GEMM, epilogue computes sum/sumsq)
//                       next layer applies BN(stats)+ReLU while loading.
// Final: conv(wh) -> mean-pool over 33 nodes -> @wc + bc.
// ---------------------------------------------------------------------------

#define NUM_JOINTS 33
#define BATCH      4096
#define NN_ROWS    (BATCH * NUM_JOINTS)   // 135168
#define HDIM       256
#define NN_INV     (1.0f / 135168.0f)

// Baked skeleton CSR (neighbors incl. self-loop) from SKELETON_EDGES
__constant__ int ADJ_OFF[34] = {
    0,3,6,9,12,15,18,21,23,25,27,29,33,37,40,43,48,53,56,59,62,65,
    67,69,73,77,80,83,87,91,94,97,100,103};
__constant__ int ADJ_NB[103] = {
    1,4,0,        // 0
    0,2,1,        // 1
    1,3,2,        // 2
    2,7,3,        // 3
    0,5,4,        // 4
    4,6,5,        // 5
    5,8,6,        // 6
    3,7,          // 7
    6,8,          // 8
    10,9,         // 9
    9,10,         // 10
    12,13,23,11,  // 11
    11,14,24,12,  // 12
    11,15,13,     // 13
    12,16,14,     // 14
    13,17,19,21,15, // 15
    14,18,20,22,16, // 16
    15,19,17,     // 17
    16,20,18,     // 18
    15,17,19,     // 19
    16,18,20,     // 20
    15,21,        // 21
    16,22,        // 22
    11,24,25,23,  // 23
    12,23,26,24,  // 24
    23,27,25,     // 25
    24,28,26,     // 26
    25,29,31,27,  // 27
    26,30,32,28,  // 28
    27,31,29,     // 29
    28,32,30,     // 30
    29,27,31,     // 31
    30,28,32};    // 32
__constant__ float DEGF[33] = {
    3,3,3,3,3,3,3,2,2,2,2,4,4,3,3,5,5,3,3,3,3,2,2,4,4,3,3,4,4,3,3,3,3};

// Scratch (device globals -- allowed; no runtime allocation)
__device__ float g_bufA[(size_t)NN_ROWS * HDIM];
__device__ float g_bufB[(size_t)NN_ROWS * HDIM];
__device__ float g_stats[3 * 512];   // per layer: [256 sum][256 sumsq]

// ---------------------------------------------------------------------------
// zero stats
// ---------------------------------------------------------------------------
__global__ void zero_stats_kernel(float* stats) {
    int i = blockIdx.x * blockDim.x + threadIdx.x;
    if (i < 3 * 512) stats[i] = 0.0f;
}

// ---------------------------------------------------------------------------
// A_hat apply: one block per graph, 256 threads = channels.
// mode 0: nan_to_num on input (layer 0), mode 1: BN(stats,g,be)+ReLU on input.
// ---------------------------------------------------------------------------
__global__ void __launch_bounds__(256)
agg_kernel(const float* __restrict__ in, float* __restrict__ out,
           const float* __restrict__ stats, const float* __restrict__ gam,
           const float* __restrict__ bet, int mode)
{
    __shared__ float s[NUM_JOINTS * HDIM];
    const int g = blockIdx.x;
    const int c = threadIdx.x;
    const size_t base = (size_t)g * NUM_JOINTS * HDIM;

    float scale = 1.0f, shift = 0.0f;
    if (mode == 1) {
        float mu  = stats[c] * NN_INV;
        float ex2 = stats[256 + c] * NN_INV;
        float var = ex2 - mu * mu;
        float inv = rsqrtf(var + 1e-5f);
        scale = inv * gam[c];
        shift = bet[c] - mu * scale;
    }

    #pragma unroll
    for (int n = 0; n < NUM_JOINTS; n++) {
        float v = in[base + n * HDIM + c];
        if (mode == 0) {
            if (isnan(v)) v = 0.0f;
            else if (isinf(v)) v = (v > 0.0f) ? FLT_MAX : -FLT_MAX;
        } else {
            v = fmaxf(fmaf(v, scale, shift), 0.0f);
        }
        s[n * HDIM + c] = v;
    }
    __syncthreads();

    #pragma unroll
    for (int n = 0; n < NUM_JOINTS; n++) {
        const int beg = ADJ_OFF[n], end = ADJ_OFF[n + 1];
        const float dn = rsqrtf(DEGF[n]);
        float acc = 0.0f;
        for (int e = beg; e < end; e++) {
            int nb = ADJ_NB[e];
            acc = fmaf(dn * rsqrtf(DEGF[nb]), s[nb * HDIM + c], acc);
        }
        out[base + n * HDIM + c] = acc;
    }
}

// ---------------------------------------------------------------------------
// GEMM: C[M,256] = A[M,256] @ W[256,256] + bias ; optional per-col sum/sumsq
// 128x128 block tile, BK=8, 256 threads, 8x8 microtile.
// ---------------------------------------------------------------------------
__global__ void __launch_bounds__(256)
gemm_bias_stats(const float* __restrict__ A, const float* __restrict__ W,
                const float* __restrict__ bias, float* __restrict__ C,
                float* __restrict__ stats)
{
    __shared__ float sA[8][128];
    __shared__ float sB[8][128];

    const int tid = threadIdx.x;
    const int tx = tid & 15;
    const int ty = tid >> 4;
    const int rowBase = blockIdx.y * 128;
    const int colBase = blockIdx.x * 128;

    const int aRow = tid >> 1;          // 0..127
    const int aK4  = (tid & 1) * 4;     // 0 or 4
    const int bRow = tid >> 5;          // 0..7
    const int bCol = (tid & 31) * 4;    // 0..124

    float acc[8][8];
    #pragma unroll
    for (int i = 0; i < 8; i++)
        #pragma unroll
        for (int j = 0; j < 8; j++) acc[i][j] = 0.0f;

    const float* Abase = A + (size_t)rowBase * HDIM;

    for (int k0 = 0; k0 < HDIM; k0 += 8) {
        float4 av = *(const float4*)(Abase + (size_t)aRow * HDIM + k0 + aK4);
        sA[aK4 + 0][aRow] = av.x;
        sA[aK4 + 1][aRow] = av.y;
        sA[aK4 + 2][aRow] = av.z;
        sA[aK4 + 3][aRow] = av.w;
        *(float4*)&sB[bRow][bCol] =
            *(const float4*)(W + (size_t)(k0 + bRow) * HDIM + colBase + bCol);
        __syncthreads();

        #pragma unroll
        for (int kk = 0; kk < 8; kk++) {
            float ra[8], rb[8];
            *(float4*)&ra[0] = *(const float4*)&sA[kk][ty * 8];
            *(float4*)&ra[4] = *(const float4*)&sA[kk][ty * 8 + 4];
            *(float4*)&rb[0] = *(const float4*)&sB[kk][tx * 8];
            *(float4*)&rb[4] = *(const float4*)&sB[kk][tx * 8 + 4];
            #pragma unroll
            for (int i = 0; i < 8; i++)
                #pragma unroll
                for (int j = 0; j < 8; j++)
                    acc[i][j] = fmaf(ra[i], rb[j], acc[i][j]);
        }
        __syncthreads();
    }

    // Epilogue: bias, store, per-column partial stats
    float bcol[8];
    #pragma unroll
    for (int j = 0; j < 8; j++) bcol[j] = bias[colBase + tx * 8 + j];

    float cs1[8], cs2[8];
    #pragma unroll
    for (int j = 0; j < 8; j++) { cs1[j] = 0.0f; cs2[j] = 0.0f; }

    #pragma unroll
    for (int i = 0; i < 8; i++) {
        float z[8];
        #pragma unroll
        for (int j = 0; j < 8; j++) {
            float zz = acc[i][j] + bcol[j];
            z[j] = zz;
            cs1[j] += zz;
            cs2[j] = fmaf(zz, zz, cs2[j]);
        }
        const int row = rowBase + ty * 8 + i;
        float4* outp = (float4*)(C + (size_t)row * HDIM + colBase + tx * 8);
        outp[0] = make_float4(z[0], z[1], z[2], z[3]);
        outp[1] = make_float4(z[4], z[5], z[6], z[7]);
    }

    if (stats != nullptr) {
        float* cs = &sA[0][0];   // reuse: [0..127]=sum, [128..255]=sumsq
        cs[tid] = 0.0f;
        __syncthreads();
        #pragma unroll
        for (int j = 0; j < 8; j++) {
            atomicAdd(&cs[tx * 8 + j], cs1[j]);
            atomicAdd(&cs[128 + tx * 8 + j], cs2[j]);
        }
        __syncthreads();
        if (tid < 128) {
            atomicAdd(&stats[colBase + tid], cs[tid]);
            atomicAdd(&stats[256 + colBase + tid], cs[128 + tid]);
        }
    }
}

// ---------------------------------------------------------------------------
// mean pool over 33 nodes + classifier [256 x 4]
// ---------------------------------------------------------------------------
__global__ void __launch_bounds__(256)
pool_kernel(const float* __restrict__ h, const float* __restrict__ wc,
            const float* __restrict__ bc, float* __restrict__ out)
{
    const int g = blockIdx.x;
    const int c = threadIdx.x;
    const size_t base = (size_t)g * NUM_JOINTS * HDIM;

    float s = 0.0f;
    #pragma unroll
    for (int n = 0; n < NUM_JOINTS; n++) s += h[base + n * HDIM + c];
    s *= (1.0f / 33.0f);

    __shared__ float red[256];
    for (int l = 0; l < 4; l++) {
        red[c] = s * wc[c * 4 + l];
        __syncthreads();
        for (int off = 128; off > 0; off >>= 1) {
            if (c < off) red[c] += red[c + off];
            __syncthreads();
        }
        if (c == 0) out[g * 4 + l] = red[0] + bc[l];
        __syncthreads();
    }
}

// ---------------------------------------------------------------------------
extern "C" void kernel_launch(void* const* d_in, const int* in_sizes, int n_in,
                              void* d_out, int out_size)
{
    const float* x   = (const float*)d_in[0];
    const float* w0  = (const float*)d_in[1];
    const float* b0  = (const float*)d_in[2];
    const float* g0  = (const float*)d_in[3];
    const float* be0 = (const float*)d_in[4];
    const float* w1  = (const float*)d_in[5];
    const float* b1  = (const float*)d_in[6];
    const float* g1  = (const float*)d_in[7];
    const float* be1 = (const float*)d_in[8];
    const float* w2  = (const float*)d_in[9];
    const float* b2  = (const float*)d_in[10];
    const float* g2  = (const float*)d_in[11];
    const float* be2 = (const float*)d_in[12];
    const float* wh  = (const float*)d_in[13];
    const float* bh  = (const float*)d_in[14];
    const float* wc  = (const float*)d_in[15];
    const float* bc  = (const float*)d_in[16];
    // d_in[17], d_in[18] (src, dst): structure is baked at compile time.

    float *bufA, *bufB, *stats;
    cudaGetSymbolAddress((void**)&bufA, g_bufA);
    cudaGetSymbolAddress((void**)&bufB, g_bufB);
    cudaGetSymbolAddress((void**)&stats, g_stats);

    zero_stats_kernel<<<6, 256>>>(stats);

    dim3 gg(2, NN_ROWS / 128);   // (256/128, 135168/128) = (2, 1056)

    // layer 0
    agg_kernel<<<BATCH, 256>>>(x, bufA, nullptr, nullptr, nullptr, 0);
    gemm_bias_stats<<<gg, 256>>>(bufA, w0, b0, bufB, stats);
    // layer 1
    agg_kernel<<<BATCH, 256>>>(bufB, bufA, stats, g0, be0, 1);
    gemm_bias_stats<<<gg, 256>>>(bufA, w1, b1, bufB, stats + 512);
    // layer 2
    agg_kernel<<<BATCH, 256>>>(bufB, bufA, stats + 512, g1, be1, 1);
    gemm_bias_stats<<<gg, 256>>>(bufA, w2, b2, bufB, stats + 1024);
    // head conv
    agg_kernel<<<BATCH, 256>>>(bufB, bufA, stats + 1024, g2, be2, 1);
    gemm_bias_stats<<<gg, 256>>>(bufA, wh, bh, bufB, nullptr);
    // pool + classify
    pool_kernel<<<BATCH, 256>>>(bufB, wc, bc, (float*)d_out);
}

// round 2
// speedup vs baseline: 1.6472x; 1.6472x over previous
#include <cuda_runtime.h>
#include <cuda_bf16.h>
#include <math.h>
#include <float.h>
#include <stdint.h>

// ---------------------------------------------------------------------------
// MultiLabelGCN on GB300 — fused (A_hat o BN o ReLU) + tf32 tensor-core GEMM.
// Per layer, one kernel: load 132-row (4-graph) x 32-col chunk, apply
// BN+ReLU (or nan_to_num for layer 0), aggregate with the baked skeleton
// stencil in smem, then m16n8k8 tf32 MMAs against the weight chunk.
// Epilogue adds bias, stores Z, and accumulates per-channel sum/sumsq for the
// next layer's BN.
// ---------------------------------------------------------------------------

#define NUM_JOINTS 33
#define BATCH      4096
#define NN_ROWS    (BATCH * NUM_JOINTS)   // 135168
#define HDIM       256
#define NN_INV     (1.0f / 135168.0f)

#define GPB    4                    // graphs per block
#define MROWS  (GPB * NUM_JOINTS)   // 132
#define MPAD   160                  // 10 x m16 tiles
#define NTILE  128
#define BK     32

// Baked skeleton CSR (neighbors incl. self-loop)
__constant__ int ADJ_OFF[34] = {
    0,3,6,9,12,15,18,21,23,25,27,29,33,37,40,43,48,53,56,59,62,65,
    67,69,73,77,80,83,87,91,94,97,100,103};
__constant__ int ADJ_NB[103] = {
    1,4,0,  0,2,1,  1,3,2,  2,7,3,  0,5,4,  4,6,5,  5,8,6,  3,7,  6,8,
    10,9,  9,10,  12,13,23,11,  11,14,24,12,  11,15,13,  12,16,14,
    13,17,19,21,15,  14,18,20,22,16,  15,19,17,  16,20,18,  15,17,19,
    16,18,20,  15,21,  16,22,  11,24,25,23,  12,23,26,24,  23,27,25,
    24,28,26,  25,29,31,27,  26,30,32,28,  27,31,29,  28,32,30,
    29,27,31,  30,28,32};
__constant__ float DEGF[33] = {
    3,3,3,3,3,3,3,2,2,2,2,4,4,3,3,5,5,3,3,3,3,2,2,4,4,3,3,4,4,3,3,3,3};

// Scratch (device globals)
__device__ float g_bufA[(size_t)NN_ROWS * HDIM];
__device__ float g_bufB[(size_t)NN_ROWS * HDIM];
__device__ float g_stats[3 * 512];   // per layer: [256 sum][256 sumsq]

__global__ void zero_stats_kernel(float* stats) {
    int i = blockIdx.x * blockDim.x + threadIdx.x;
    if (i < 3 * 512) stats[i] = 0.0f;
}

// ---------------------------------------------------------------------------
__device__ __forceinline__ uint32_t f2tf32(float f) {
    uint32_t u;
    asm("cvt.rna.tf32.f32 %0, %1;" : "=r"(u) : "f"(f));
    return u;
}

__device__ __forceinline__ void mma_tf32(float* d, const uint32_t* a, const uint32_t* b) {
    asm volatile(
        "mma.sync.aligned.m16n8k8.row.col.f32.tf32.tf32.f32 "
        "{%0,%1,%2,%3}, {%4,%5,%6,%7}, {%8,%9}, {%0,%1,%2,%3};\n"
        : "+f"(d[0]), "+f"(d[1]), "+f"(d[2]), "+f"(d[3])
        : "r"(a[0]), "r"(a[1]), "r"(a[2]), "r"(a[3]), "r"(b[0]), "r"(b[1]));
}

// ---------------------------------------------------------------------------
// Fused layer kernel. mode 0: nan_to_num input; mode 1: BN(stats)+ReLU input.
// grid = (HDIM/NTILE, NN_ROWS/MROWS) = (2, 1024), block = 256.
// ---------------------------------------------------------------------------
__global__ void __launch_bounds__(256, 2)
fused_layer(const float* __restrict__ in, const float* __restrict__ W,
            const float* __restrict__ bias, float* __restrict__ out,
            const float* __restrict__ stats_in, const float* __restrict__ gam,
            const float* __restrict__ bet, float* __restrict__ stats_out,
            int mode)
{
    __shared__ float sRaw[MROWS][36];
    __shared__ float sA[MPAD][36];
    __shared__ float sB[BK][136];
    __shared__ float sNW[103];
    __shared__ float sScale[256];
    __shared__ float sShift[256];
    __shared__ float sStat[256];

    const int tid  = threadIdx.x;
    const int lane = tid & 31;
    const int warp = tid >> 5;
    const int wm   = warp >> 2;   // 0..1 (80 rows each)
    const int wn   = warp & 3;    // 0..3 (32 cols each)
    const int rowBase = blockIdx.y * MROWS;
    const int colBase = blockIdx.x * NTILE;

    // stencil weights
    if (tid < NUM_JOINTS) {
        float dn = rsqrtf(DEGF[tid]);
        for (int e = ADJ_OFF[tid]; e < ADJ_OFF[tid + 1]; e++)
            sNW[e] = dn * rsqrtf(DEGF[ADJ_NB[e]]);
    }
    // BN coefficients for all 256 channels
    if (mode == 1) {
        float mu  = stats_in[tid] * NN_INV;
        float ex2 = stats_in[256 + tid] * NN_INV;
        float inv = rsqrtf(ex2 - mu * mu + 1e-5f);
        float sc  = inv * gam[tid];
        sScale[tid] = sc;
        sShift[tid] = bet[tid] - mu * sc;
    }
    // zero padded rows of sA (stay zero across chunks)
    for (int i = tid; i < (MPAD - MROWS) * 36; i += 256)
        sA[MROWS + i / 36][i % 36] = 0.0f;

    float acc[5][4][4];
    #pragma unroll
    for (int i = 0; i < 5; i++)
        #pragma unroll
        for (int nt = 0; nt < 4; nt++)
            #pragma unroll
            for (int j = 0; j < 4; j++) acc[i][nt][j] = 0.0f;

    for (int k0 = 0; k0 < HDIM; k0 += BK) {
        __syncthreads();
        // ---- load 132 x 32 raw chunk, apply BN+ReLU / nan_to_num ----
        {
            const int r0 = tid >> 3;
            const int cc = (tid & 7) * 4;
            for (int rr = r0; rr < MROWS; rr += 32) {
                float4 v = *(const float4*)(in + (size_t)(rowBase + rr) * HDIM + k0 + cc);
                float vv[4] = {v.x, v.y, v.z, v.w};
                #pragma unroll
                for (int j = 0; j < 4; j++) {
                    float f = vv[j];
                    if (mode == 0) {
                        if (isnan(f)) f = 0.0f;
                        else if (isinf(f)) f = (f > 0.0f) ? FLT_MAX : -FLT_MAX;
                    } else {
                        f = fmaxf(fmaf(f, sScale[k0 + cc + j], sShift[k0 + cc + j]), 0.0f);
                    }
                    sRaw[rr][cc + j] = f;
                }
            }
        }
        // ---- load W chunk 32 x 128 ----
        {
            const int r0 = tid >> 5;
            const int cc = (tid & 31) * 4;
            #pragma unroll
            for (int rr = r0; rr < BK; rr += 8) {
                float4 v = *(const float4*)(W + (size_t)(k0 + rr) * HDIM + colBase + cc);
                *(float4*)&sB[rr][cc] = v;
            }
        }
        __syncthreads();
        // ---- aggregate with skeleton stencil ----
        {
            const int c = tid & 31;
            for (int r = tid >> 5; r < MROWS; r += 8) {
                int g  = r / NUM_JOINTS;
                int n  = r - g * NUM_JOINTS;
                int gb = g * NUM_JOINTS;
                float a = 0.0f;
                int e1 = ADJ_OFF[n + 1];
                for (int e = ADJ_OFF[n]; e < e1; e++)
                    a = fmaf(sNW[e], sRaw[gb + ADJ_NB[e]][c], a);
                sA[r][c] = a;
            }
        }
        __syncthreads();
        // ---- tensor core MMAs: 4 k8-steps ----
        #pragma unroll
        for (int ks = 0; ks < 4; ks++) {
            const int kk = ks * 8;
            uint32_t bf[4][2];
            #pragma unroll
            for (int nt = 0; nt < 4; nt++) {
                int col = wn * 32 + nt * 8 + (lane >> 2);
                bf[nt][0] = f2tf32(sB[kk + (lane & 3)][col]);
                bf[nt][1] = f2tf32(sB[kk + 4 + (lane & 3)][col]);
            }
            #pragma unroll
            for (int i = 0; i < 5; i++) {
                int r0 = wm * 80 + i * 16 + (lane >> 2);
                uint32_t af[4];
                af[0] = f2tf32(sA[r0][kk + (lane & 3)]);
                af[1] = f2tf32(sA[r0 + 8][kk + (lane & 3)]);
                af[2] = f2tf32(sA[r0][kk + 4 + (lane & 3)]);
                af[3] = f2tf32(sA[r0 + 8][kk + 4 + (lane & 3)]);
                #pragma unroll
                for (int nt = 0; nt < 4; nt++)
                    mma_tf32(acc[i][nt], af, bf[nt]);
            }
        }
    }

    // ---- epilogue: bias, store, stats ----
    float bval[8];
    #pragma unroll
    for (int nt = 0; nt < 4; nt++) {
        int col = colBase + wn * 32 + nt * 8 + 2 * (lane & 3);
        bval[nt * 2 + 0] = bias[col];
        bval[nt * 2 + 1] = bias[col + 1];
    }
    float cs1[8], cs2[8];
    #pragma unroll
    for (int j = 0; j < 8; j++) { cs1[j] = 0.0f; cs2[j] = 0.0f; }

    #pragma unroll
    for (int i = 0; i < 5; i++) {
        int rb = wm * 80 + i * 16 + (lane >> 2);
        #pragma unroll
        for (int nt = 0; nt < 4; nt++) {
            int col = colBase + wn * 32 + nt * 8 + 2 * (lane & 3);
            if (rb < MROWS) {
                float z0 = acc[i][nt][0] + bval[nt * 2 + 0];
                float z1 = acc[i][nt][1] + bval[nt * 2 + 1];
                float2 st = make_float2(z0, z1);
                *(float2*)(out + (size_t)(rowBase + rb) * HDIM + col) = st;
                cs1[nt * 2 + 0] += z0; cs2[nt * 2 + 0] = fmaf(z0, z0, cs2[nt * 2 + 0]);
                cs1[nt * 2 + 1] += z1; cs2[nt * 2 + 1] = fmaf(z1, z1, cs2[nt * 2 + 1]);
            }
            int r2 = rb + 8;
            if (r2 < MROWS) {
                float z2 = acc[i][nt][2] + bval[nt * 2 + 0];
                float z3 = acc[i][nt][3] + bval[nt * 2 + 1];
                float2 st = make_float2(z2, z3);
                *(float2*)(out + (size_t)(rowBase + r2) * HDIM + col) = st;
                cs1[nt * 2 + 0] += z2; cs2[nt * 2 + 0] = fmaf(z2, z2, cs2[nt * 2 + 0]);
                cs1[nt * 2 + 1] += z3; cs2[nt * 2 + 1] = fmaf(z3, z3, cs2[nt * 2 + 1]);
            }
        }
    }

    if (stats_out != nullptr) {
        __syncthreads();
        sStat[tid] = 0.0f;
        __syncthreads();
        #pragma unroll
        for (int j = 0; j < 8; j++) {
            int cl = wn * 32 + (j >> 1) * 8 + 2 * (lane & 3) + (j & 1);
            atomicAdd(&sStat[cl], cs1[j]);
            atomicAdd(&sStat[128 + cl], cs2[j]);
        }
        __syncthreads();
        if (tid < 128) {
            atomicAdd(&stats_out[colBase + tid], sStat[tid]);
            atomicAdd(&stats_out[256 + colBase + tid], sStat[128 + tid]);
        }
    }
}

// ---------------------------------------------------------------------------
// final head: BN+ReLU was already folded into the last fused_layer's input;
// here input is Z3 = conv(wh) output -> mean pool over 33 nodes -> @wc + bc
// ---------------------------------------------------------------------------
__global__ void __launch_bounds__(256)
pool_kernel(const float* __restrict__ h, const float* __restrict__ wc,
            const float* __restrict__ bc, float* __restrict__ out)
{
    const int g = blockIdx.x;
    const int c = threadIdx.x;
    const size_t base = (size_t)g * NUM_JOINTS * HDIM;

    float s = 0.0f;
    #pragma unroll
    for (int n = 0; n < NUM_JOINTS; n++) s += h[base + n * HDIM + c];
    s *= (1.0f / 33.0f);

    __shared__ float red[256];
    for (int l = 0; l < 4; l++) {
        red[c] = s * wc[c * 4 + l];
        __syncthreads();
        for (int off = 128; off > 0; off >>= 1) {
            if (c < off) red[c] += red[c + off];
            __syncthreads();
        }
        if (c == 0) out[g * 4 + l] = red[0] + bc[l];
        __syncthreads();
    }
}

// ---------------------------------------------------------------------------
extern "C" void kernel_launch(void* const* d_in, const int* in_sizes, int n_in,
                              void* d_out, int out_size)
{
    const float* x   = (const float*)d_in[0];
    const float* w0  = (const float*)d_in[1];
    const float* b0  = (const float*)d_in[2];
    const float* g0  = (const float*)d_in[3];
    const float* be0 = (const float*)d_in[4];
    const float* w1  = (const float*)d_in[5];
    const float* b1  = (const float*)d_in[6];
    const float* g1  = (const float*)d_in[7];
    const float* be1 = (const float*)d_in[8];
    const float* w2  = (const float*)d_in[9];
    const float* b2  = (const float*)d_in[10];
    const float* g2  = (const float*)d_in[11];
    const float* be2 = (const float*)d_in[12];
    const float* wh  = (const float*)d_in[13];
    const float* bh  = (const float*)d_in[14];
    const float* wc  = (const float*)d_in[15];
    const float* bc  = (const float*)d_in[16];

    float *bufA, *bufB, *stats;
    cudaGetSymbolAddress((void**)&bufA, g_bufA);
    cudaGetSymbolAddress((void**)&bufB, g_bufB);
    cudaGetSymbolAddress((void**)&stats, g_stats);

    zero_stats_kernel<<<6, 256>>>(stats);

    dim3 gg(HDIM / NTILE, NN_ROWS / MROWS);   // (2, 1024)

    // layer 0: agg(nan_to_num(x)) @ w0 + b0, stats0
    fused_layer<<<gg, 256>>>(x,    w0, b0, bufB, nullptr, nullptr, nullptr, stats, 0);
    // layer 1: agg(BN0+ReLU(Z0)) @ w1 + b1, stats1
    fused_layer<<<gg, 256>>>(bufB, w1, b1, bufA, stats,        g0, be0, stats + 512, 1);
    // layer 2
    fused_layer<<<gg, 256>>>(bufA, w2, b2, bufB, stats + 512,  g1, be1, stats + 1024, 1);
    // head conv
    fused_layer<<<gg, 256>>>(bufB, wh, bh, bufA, stats + 1024, g2, be2, nullptr, 1);
    // pool + classify
    pool_kernel<<<BATCH, 256>>>(bufA, wc, bc, (float*)d_out);
}

// round 4
// speedup vs baseline: 1.8920x; 1.1487x over previous
#include <cuda_runtime.h>
#include <cuda_bf16.h>
#include <math.h>
#include <float.h>
#include <stdint.h>

// ---------------------------------------------------------------------------
// MultiLabelGCN on GB300 — fused (A_hat o BN o ReLU) + tf32 MMA, pipelined.
//  * W pre-packed to tf32 fragment pairs once per call (pack_w kernel).
//  * A aggregates stored in smem as tf32 (k,k+4) pairs -> LDS.64 fragments.
//  * cp.async double-buffered W tiles (issue AFTER the barrier that retires
//    the MMA reading the victim buffer — fixes Round-3 race).
// ---------------------------------------------------------------------------

#define NUM_JOINTS 33
#define BATCH      4096
#define NN_ROWS    (BATCH * NUM_JOINTS)   // 135168
#define HDIM       256
#define NN_INV     (1.0f / 135168.0f)

#define GPB    4
#define MROWS  (GPB * NUM_JOINTS)   // 132
#define MPAD   160                  // 10 x m16
#define NTILE  128
#define BK     32
#define NCHUNK (HDIM / BK)          // 8

// smem layout (bytes)
#define OFF_RAW    0                       // float [132][36]            19008
#define OFF_A2     19008                   // uint32 [160*40]            25600
#define OFF_B2     44608                   // uint32 [2][128*40]         40960
#define OFF_NW     85568                   // float [103]                  412
#define OFF_SCALE  85980                   // float [256]                 1024
#define OFF_SHIFT  87004                   // float [256]                 1024
#define OFF_STAT   88028                   // float [256]                 1024
#define SMEM_BYTES 89088

__constant__ int ADJ_OFF[34] = {
    0,3,6,9,12,15,18,21,23,25,27,29,33,37,40,43,48,53,56,59,62,65,
    67,69,73,77,80,83,87,91,94,97,100,103};
__constant__ int ADJ_NB[103] = {
    1,4,0,  0,2,1,  1,3,2,  2,7,3,  0,5,4,  4,6,5,  5,8,6,  3,7,  6,8,
    10,9,  9,10,  12,13,23,11,  11,14,24,12,  11,15,13,  12,16,14,
    13,17,19,21,15,  14,18,20,22,16,  15,19,17,  16,20,18,  15,17,19,
    16,18,20,  15,21,  16,22,  11,24,25,23,  12,23,26,24,  23,27,25,
    24,28,26,  25,29,31,27,  26,30,32,28,  27,31,29,  28,32,30,
    29,27,31,  30,28,32};
__constant__ float DEGF[33] = {
    3,3,3,3,3,3,3,2,2,2,2,4,4,3,3,5,5,3,3,3,3,2,2,4,4,3,3,4,4,3,3,3,3};

// scratch
__device__ float g_bufA[(size_t)NN_ROWS * HDIM];
__device__ float g_bufB[(size_t)NN_ROWS * HDIM];
__device__ float g_stats[3 * 512];
__device__ uint2 g_wpack[4 * 8 * 256 * 16];   // [mat][chunk][col][kpair]

// ---------------------------------------------------------------------------
__device__ __forceinline__ uint32_t f2tf32(float f) {
    uint32_t u;
    asm("cvt.rna.tf32.f32 %0, %1;" : "=r"(u) : "f"(f));
    return u;
}
__device__ __forceinline__ void mma_tf32(float* d, const uint32_t* a, const uint32_t* b) {
    asm volatile(
        "mma.sync.aligned.m16n8k8.row.col.f32.tf32.tf32.f32 "
        "{%0,%1,%2,%3}, {%4,%5,%6,%7}, {%8,%9}, {%0,%1,%2,%3};\n"
        : "+f"(d[0]), "+f"(d[1]), "+f"(d[2]), "+f"(d[3])
        : "r"(a[0]), "r"(a[1]), "r"(a[2]), "r"(a[3]), "r"(b[0]), "r"(b[1]));
}
__device__ __forceinline__ void cp16(void* dst, const void* src) {
    uint32_t d = (uint32_t)__cvta_generic_to_shared(dst);
    asm volatile("cp.async.cg.shared.global [%0], [%1], 16;\n" :: "r"(d), "l"(src));
}
#define CP_COMMIT() asm volatile("cp.async.commit_group;\n")
#define CP_WAIT1()  asm volatile("cp.async.wait_group 1;\n")

// ---------------------------------------------------------------------------
// pack weights -> tf32 pairs. pair (m,c0,col,kp): k = c0*32 + (kp>>2)*8 + (kp&3)
// ---------------------------------------------------------------------------
__global__ void pack_w(const float* __restrict__ w0, const float* __restrict__ w1,
                       const float* __restrict__ w2, const float* __restrict__ wh)
{
    int idx = blockIdx.x * blockDim.x + threadIdx.x;   // 0..131071
    int kp  = idx & 15;
    int col = (idx >> 4) & 255;
    int c0  = (idx >> 12) & 7;
    int m   = idx >> 15;
    const float* W = (m == 0) ? w0 : (m == 1) ? w1 : (m == 2) ? w2 : wh;
    int k = c0 * 32 + ((kp >> 2) * 8) + (kp & 3);
    uint2 v;
    v.x = f2tf32(W[(size_t)k * HDIM + col]);
    v.y = f2tf32(W[(size_t)(k + 4) * HDIM + col]);
    g_wpack[idx] = v;
}

__global__ void zero_stats_kernel(float* stats) {
    int i = blockIdx.x * blockDim.x + threadIdx.x;
    if (i < 3 * 512) stats[i] = 0.0f;
}

// ---------------------------------------------------------------------------
// fused layer. grid=(2,1024), block=256, dynamic smem SMEM_BYTES.
// ---------------------------------------------------------------------------
__global__ void __launch_bounds__(256, 2)
fused_layer(const float* __restrict__ in, int wsel, const float* __restrict__ bias,
            float* __restrict__ out, const float* __restrict__ stats_in,
            const float* __restrict__ gam, const float* __restrict__ bet,
            float* __restrict__ stats_out, int mode)
{
    extern __shared__ char smem[];
    float (*sRaw)[36]  = (float(*)[36])(smem + OFF_RAW);
    uint32_t* sA2      = (uint32_t*)(smem + OFF_A2);
    uint32_t* sB2      = (uint32_t*)(smem + OFF_B2);
    float* sNW         = (float*)(smem + OFF_NW);
    float* sScale      = (float*)(smem + OFF_SCALE);
    float* sShift      = (float*)(smem + OFF_SHIFT);
    float* sStat       = (float*)(smem + OFF_STAT);

    const int tid = threadIdx.x, lane = tid & 31, warp = tid >> 5;
    const int wm = warp >> 2, wn = warp & 3;
    const int rowBase = blockIdx.y * MROWS;
    const int colBase = blockIdx.x * NTILE;

    if (tid < NUM_JOINTS) {
        float dn = rsqrtf(DEGF[tid]);
        for (int e = ADJ_OFF[tid]; e < ADJ_OFF[tid + 1]; e++)
            sNW[e] = dn * rsqrtf(DEGF[ADJ_NB[e]]);
    }
    if (mode == 1) {
        float mu  = stats_in[tid] * NN_INV;
        float ex2 = stats_in[256 + tid] * NN_INV;
        float inv = rsqrtf(ex2 - mu * mu + 1e-5f);
        float sc  = inv * gam[tid];
        sScale[tid] = sc;
        sShift[tid] = bet[tid] - mu * sc;
    }
    // zero pad rows once (never rewritten)
    for (int i = tid; i < (MPAD - MROWS) * 40; i += 256) sA2[MROWS * 40 + i] = 0;

    const uint2* wbase = g_wpack + (size_t)wsel * (8 * 256 * 16);

    // prefetch input chunk 0
    const int pr0 = tid >> 3;          // 0..31
    const int pcc = (tid & 7) * 4;     // 0..28
    float4 pin[5];
    #pragma unroll
    for (int it = 0; it < 5; it++) {
        int rr = pr0 + 32 * it;
        if (rr < MROWS)
            pin[it] = *(const float4*)(in + (size_t)(rowBase + rr) * HDIM + pcc);
    }
    // cp.async W chunk 0 -> buffer 0
    #pragma unroll
    for (int i = 0; i < 4; i++) {
        int idx = tid + 256 * i;       // 0..1023
        int col_l = idx >> 3, seg = idx & 7;
        cp16((char*)sB2 + col_l * 160 + seg * 16,
             (const char*)(wbase + ((size_t)(colBase + col_l) * 16 + seg * 2)));
    }
    CP_COMMIT();
    __syncthreads();   // sNW/sScale/pad ready

    float acc[5][4][4];
    #pragma unroll
    for (int i = 0; i < 5; i++)
        #pragma unroll
        for (int nt = 0; nt < 4; nt++)
            #pragma unroll
            for (int j = 0; j < 4; j++) acc[i][nt][j] = 0.0f;

    for (int c = 0; c < NCHUNK; c++) {
        const int k0 = c * BK;
        uint32_t* sBcur = sB2 + (c & 1) * 5120;

        // BN+ReLU / nan_to_num: regs -> sRaw
        #pragma unroll
        for (int it = 0; it < 5; it++) {
            int rr = pr0 + 32 * it;
            if (rr < MROWS) {
                float v[4] = {pin[it].x, pin[it].y, pin[it].z, pin[it].w};
                #pragma unroll
                for (int j = 0; j < 4; j++) {
                    float f = v[j];
                    if (mode == 0) {
                        if (isnan(f)) f = 0.0f;
                        else if (isinf(f)) f = (f > 0.0f) ? FLT_MAX : -FLT_MAX;
                    } else {
                        f = fmaxf(fmaf(f, sScale[k0 + pcc + j], sShift[k0 + pcc + j]), 0.0f);
                    }
                    sRaw[rr][pcc + j] = f;
                }
            }
        }
        __syncthreads();   // sRaw ready; MMA of chunk c-1 retired by ALL warps

        // Safe point: buffer (c+1)&1 was last read by MMA of chunk c-1, which
        // every warp has now finished. Issue next W tile here (fixes race).
        if (c + 1 < NCHUNK) {
            uint32_t* sBn = sB2 + ((c + 1) & 1) * 5120;
            #pragma unroll
            for (int i = 0; i < 4; i++) {
                int idx = tid + 256 * i;
                int col_l = idx >> 3, seg = idx & 7;
                cp16((char*)sBn + col_l * 160 + seg * 16,
                     (const char*)(wbase + ((size_t)((c + 1) * 256 + colBase + col_l) * 16 + seg * 2)));
            }
        }
        CP_COMMIT();       // empty group on last iteration keeps counts aligned

        // aggregate -> sA2 as tf32, bank-bijective write
        {
            const int ch = lane;
            const int widx = ((ch >> 3) * 4 + (ch & 3)) * 2 + ((ch >> 2) & 1);
            for (int r = warp; r < MROWS; r += 8) {
                int g  = r / NUM_JOINTS;
                int n  = r - g * NUM_JOINTS;
                int gb = g * NUM_JOINTS;
                float a = 0.0f;
                int e1 = ADJ_OFF[n + 1];
                for (int e = ADJ_OFF[n]; e < e1; e++)
                    a = fmaf(sNW[e], sRaw[gb + ADJ_NB[e]][ch], a);
                sA2[r * 40 + widx] = f2tf32(a);
            }
        }
        // prefetch next input chunk (global, independent of smem phases)
        if (c + 1 < NCHUNK) {
            #pragma unroll
            for (int it = 0; it < 5; it++) {
                int rr = pr0 + 32 * it;
                if (rr < MROWS)
                    pin[it] = *(const float4*)(in + (size_t)(rowBase + rr) * HDIM + k0 + BK + pcc);
            }
        }
        CP_WAIT1();
        __syncthreads();   // sA2 + W[c] ready

        // MMA: 4 k8 steps, LDS.64 fragments
        #pragma unroll
        for (int ks = 0; ks < 4; ks++) {
            uint2 bfr[4];
            #pragma unroll
            for (int nt = 0; nt < 4; nt++) {
                int col_l = wn * 32 + nt * 8 + (lane >> 2);
                bfr[nt] = *(const uint2*)&sBcur[col_l * 40 + (ks * 4 + (lane & 3)) * 2];
            }
            #pragma unroll
            for (int i = 0; i < 5; i++) {
                int r = wm * 80 + i * 16 + (lane >> 2);
                uint2 p0 = *(const uint2*)&sA2[r * 40 + (ks * 4 + (lane & 3)) * 2];
                uint2 p1 = *(const uint2*)&sA2[(r + 8) * 40 + (ks * 4 + (lane & 3)) * 2];
                uint32_t af[4] = {p0.x, p1.x, p0.y, p1.y};
                #pragma unroll
                for (int nt = 0; nt < 4; nt++)
                    mma_tf32(acc[i][nt], af, (const uint32_t*)&bfr[nt]);
            }
        }
    }

    // ---- epilogue: bias, store, stats ----
    float bval[8];
    #pragma unroll
    for (int nt = 0; nt < 4; nt++) {
        int col = colBase + wn * 32 + nt * 8 + 2 * (lane & 3);
        bval[nt * 2 + 0] = bias[col];
        bval[nt * 2 + 1] = bias[col + 1];
    }
    float cs1[8], cs2[8];
    #pragma unroll
    for (int j = 0; j < 8; j++) { cs1[j] = 0.0f; cs2[j] = 0.0f; }

    #pragma unroll
    for (int i = 0; i < 5; i++) {
        int rb = wm * 80 + i * 16 + (lane >> 2);
        #pragma unroll
        for (int nt = 0; nt < 4; nt++) {
            int col = colBase + wn * 32 + nt * 8 + 2 * (lane & 3);
            if (rb < MROWS) {
                float z0 = acc[i][nt][0] + bval[nt * 2 + 0];
                float z1 = acc[i][nt][1] + bval[nt * 2 + 1];
                *(float2*)(out + (size_t)(rowBase + rb) * HDIM + col) = make_float2(z0, z1);
                cs1[nt * 2 + 0] += z0; cs2[nt * 2 + 0] = fmaf(z0, z0, cs2[nt * 2 + 0]);
                cs1[nt * 2 + 1] += z1; cs2[nt * 2 + 1] = fmaf(z1, z1, cs2[nt * 2 + 1]);
            }
            int r2 = rb + 8;
            if (r2 < MROWS) {
                float z2 = acc[i][nt][2] + bval[nt * 2 + 0];
                float z3 = acc[i][nt][3] + bval[nt * 2 + 1];
                *(float2*)(out + (size_t)(rowBase + r2) * HDIM + col) = make_float2(z2, z3);
                cs1[nt * 2 + 0] += z2; cs2[nt * 2 + 0] = fmaf(z2, z2, cs2[nt * 2 + 0]);
                cs1[nt * 2 + 1] += z3; cs2[nt * 2 + 1] = fmaf(z3, z3, cs2[nt * 2 + 1]);
            }
        }
    }

    if (stats_out != nullptr) {
        __syncthreads();
        sStat[tid] = 0.0f;
        __syncthreads();
        #pragma unroll
        for (int j = 0; j < 8; j++) {
            int cl = wn * 32 + (j >> 1) * 8 + 2 * (lane & 3) + (j & 1);
            atomicAdd(&sStat[cl], cs1[j]);
            atomicAdd(&sStat[128 + cl], cs2[j]);
        }
        __syncthreads();
        if (tid < 128) {
            atomicAdd(&stats_out[colBase + tid], sStat[tid]);
            atomicAdd(&stats_out[256 + colBase + tid], sStat[128 + tid]);
        }
    }
}

// ---------------------------------------------------------------------------
// mean pool + classifier, shfl reduction
// ---------------------------------------------------------------------------
__global__ void __launch_bounds__(256)
pool_kernel(const float* __restrict__ h, const float* __restrict__ wc,
            const float* __restrict__ bc, float* __restrict__ out)
{
    const int g = blockIdx.x;
    const int tid = threadIdx.x;
    const int lane = tid & 31, warp = tid >> 5;
    const size_t base = (size_t)g * NUM_JOINTS * HDIM;

    float s = 0.0f;
    #pragma unroll
    for (int n = 0; n < NUM_JOINTS; n++) s += h[base + n * HDIM + tid];
    s *= (1.0f / 33.0f);

    float4 wv = *(const float4*)(wc + tid * 4);
    float p0 = s * wv.x, p1 = s * wv.y, p2 = s * wv.z, p3 = s * wv.w;
    #pragma unroll
    for (int off = 16; off > 0; off >>= 1) {
        p0 += __shfl_down_sync(0xFFFFFFFF, p0, off);
        p1 += __shfl_down_sync(0xFFFFFFFF, p1, off);
        p2 += __shfl_down_sync(0xFFFFFFFF, p2, off);
        p3 += __shfl_down_sync(0xFFFFFFFF, p3, off);
    }
    __shared__ float4 part[8];
    if (lane == 0) part[warp] = make_float4(p0, p1, p2, p3);
    __syncthreads();
    if (tid == 0) {
        float4 t = make_float4(bc[0], bc[1], bc[2], bc[3]);
        #pragma unroll
        for (int w = 0; w < 8; w++) {
            t.x += part[w].x; t.y += part[w].y; t.z += part[w].z; t.w += part[w].w;
        }
        *(float4*)(out + g * 4) = t;
    }
}

// ---------------------------------------------------------------------------
extern "C" void kernel_launch(void* const* d_in, const int* in_sizes, int n_in,
                              void* d_out, int out_size)
{
    const float* x   = (const float*)d_in[0];
    const float* w0  = (const float*)d_in[1];
    const float* b0  = (const float*)d_in[2];
    const float* g0  = (const float*)d_in[3];
    const float* be0 = (const float*)d_in[4];
    const float* w1  = (const float*)d_in[5];
    const float* b1  = (const float*)d_in[6];
    const float* g1  = (const float*)d_in[7];
    const float* be1 = (const float*)d_in[8];
    const float* w2  = (const float*)d_in[9];
    const float* b2  = (const float*)d_in[10];
    const float* g2  = (const float*)d_in[11];
    const float* be2 = (const float*)d_in[12];
    const float* wh  = (const float*)d_in[13];
    const float* bh  = (const float*)d_in[14];
    const float* wc  = (const float*)d_in[15];
    const float* bc  = (const float*)d_in[16];

    float *bufA, *bufB, *stats;
    cudaGetSymbolAddress((void**)&bufA, g_bufA);
    cudaGetSymbolAddress((void**)&bufB, g_bufB);
    cudaGetSymbolAddress((void**)&stats, g_stats);

    cudaFuncSetAttribute(fused_layer, cudaFuncAttributeMaxDynamicSharedMemorySize,
                         SMEM_BYTES);

    pack_w<<<512, 256>>>(w0, w1, w2, wh);
    zero_stats_kernel<<<6, 256>>>(stats);

    dim3 gg(HDIM / NTILE, NN_ROWS / MROWS);   // (2, 1024)

    fused_layer<<<gg, 256, SMEM_BYTES>>>(x,    0, b0, bufB, nullptr, nullptr, nullptr, stats, 0);
    fused_layer<<<gg, 256, SMEM_BYTES>>>(bufB, 1, b1, bufA, stats,        g0, be0, stats + 512, 1);
    fused_layer<<<gg, 256, SMEM_BYTES>>>(bufA, 2, b2, bufB, stats + 512,  g1, be1, stats + 1024, 1);
    fused_layer<<<gg, 256, SMEM_BYTES>>>(bufB, 3, bh, bufA, stats + 1024, g2, be2, nullptr, 1);
    pool_kernel<<<BATCH, 256>>>(bufA, wc, bc, (float*)d_out);
}